// round 6
// baseline (speedup 1.0000x reference)
#include <cuda_runtime.h>

// ---------------------------------------------------------------------------
// TiDHy reference collapses analytically (validated R3/R4, rel_err 1.2e-7):
//   r zeroed each step, r2 stays zero  =>  hypernet/temporal path dead.
//   sl_rhat = (1/B) * sum_{b,t=0..T-1,d} (b_sd[d]-X[b,t,d])^2
//   sl_rbar = (1/B) * sum_{b,t=1..T-1,d} (b_sd[d]-X[b,t,d])^2
//   temp_loss = r2_losses = 0; r0, r2 outputs = zeros.
//
// R5: single fused kernel. One wave (256x1024), 2 front-batched float4 loads
// per thread, fp32 tree reduce, ticketed last-block finalize (deterministic
// fixed-order double reduce of 256 partials) — eliminates the 6.3us
// second-launch finalize kernel from R4.
// ---------------------------------------------------------------------------

static constexpr int Bn  = 128;
static constexpr int T   = 32;
static constexpr int D   = 512;
static constexpr int N4  = Bn * T * D / 4;      // 524288 float4 (8 MB)
static constexpr int BLK = 1024;
static constexpr int GRID = 256;                // 262144 threads = 1 wave
static constexpr int HALF = GRID * BLK;         // 262144 (= N4/2)

__device__ float        g_pa[GRID];             // per-block partial: sum all t
__device__ float        g_pt[GRID];             // per-block partial: t==0 slice
__device__ unsigned int g_done;                 // self-wrapping completion ticket

__global__ __launch_bounds__(BLK)
void tidhy_fused_kernel(const float4* __restrict__ X4,
                        const float4* __restrict__ bsd4,
                        float* __restrict__ out, int out_size)
{
    const int tid = blockIdx.x * BLK + threadIdx.x;

    // ---- zero-fill output tail (scalars [0..3] written by finalizer) ----
    for (int i = 4 + tid; i < out_size; i += HALF)
        out[i] = 0.0f;

    // ---- two front-batched coalesced loads per thread (max MLP) ----
    // i1 = tid + HALF: since HALF/128 = 2048 ≡ 0 (mod 32), both indices share
    // the same t = (i/128) mod 32 and the same d4 = i mod 128.
    float4 x0 = X4[tid];
    float4 x1 = X4[tid + HALF];
    float4 b  = bsd4[tid & (D / 4 - 1)];        // 2 KB vector, L1 broadcast
    const int t = (tid >> 7) & (T - 1);

    float a0 = b.x - x0.x, a1 = b.y - x0.y, a2 = b.z - x0.z, a3 = b.w - x0.w;
    float c0 = b.x - x1.x, c1 = b.y - x1.y, c2 = b.z - x1.z, c3 = b.w - x1.w;
    float v = a0*a0 + a1*a1 + a2*a2 + a3*a3
            + c0*c0 + c1*c1 + c2*c2 + c3*c3;
    float v0 = (t == 0) ? v : 0.0f;

    // ---- warp tree reduce (fp32, two sums pipelined) ----
    #pragma unroll
    for (int o = 16; o > 0; o >>= 1) {
        v  += __shfl_down_sync(0xffffffffu, v,  o);
        v0 += __shfl_down_sync(0xffffffffu, v0, o);
    }

    __shared__ float sh_all[32], sh_t0[32];
    const int lane = threadIdx.x & 31;
    const int wrp  = threadIdx.x >> 5;
    if (lane == 0) { sh_all[wrp] = v; sh_t0[wrp] = v0; }
    __syncthreads();

    if (wrp != 0) return;                       // only warp 0 continues

    v  = sh_all[lane];
    v0 = sh_t0[lane];
    #pragma unroll
    for (int o = 16; o > 0; o >>= 1) {
        v  += __shfl_down_sync(0xffffffffu, v,  o);
        v0 += __shfl_down_sync(0xffffffffu, v0, o);
    }

    // ---- publish block partial + ticket ----
    unsigned int ticket = 0;
    if (lane == 0) {
        g_pa[blockIdx.x] = v;
        g_pt[blockIdx.x] = v0;
        __threadfence();
        // wraps to 0 when old == GRID-1 → self-resets for next graph replay
        ticket = atomicInc(&g_done, GRID - 1);
    }
    ticket = __shfl_sync(0xffffffffu, ticket, 0);
    if (ticket != GRID - 1) return;

    // ---- last block's warp 0: deterministic fixed-order finalize ----
    __threadfence();                            // acquire: partials visible
    double s = 0.0, s0 = 0.0;
    #pragma unroll
    for (int j = 0; j < GRID / 32; j++) {       // 8 partials per lane, L2 hits
        s  += (double)__ldcg(&g_pa[lane + j * 32]);
        s0 += (double)__ldcg(&g_pt[lane + j * 32]);
    }
    #pragma unroll
    for (int o = 16; o > 0; o >>= 1) {
        s  += __shfl_down_sync(0xffffffffu, s,  o);
        s0 += __shfl_down_sync(0xffffffffu, s0, o);
    }
    if (lane == 0) {
        out[0] = (float)(s / (double)Bn);          // sl_rhat  (t = 0..T-1)
        out[1] = (float)((s - s0) / (double)Bn);   // sl_rbar  (t = 1..T-1)
        out[2] = 0.0f;                             // temp_loss
        out[3] = 0.0f;                             // r2_losses
    }
}

extern "C" void kernel_launch(void* const* d_in, const int* in_sizes, int n_in,
                              void* d_out, int out_size)
{
    // metadata order: X, rng, W_sd, b_sd, W_h1, b_h1, ln_scale, ln_bias,
    //                 W_h2, b_h2, W_h3, b_h3, temporal
    const float4* X4   = (const float4*)d_in[0];
    const float4* bsd4 = (const float4*)d_in[3];
    float* out = (float*)d_out;

    tidhy_fused_kernel<<<GRID, BLK>>>(X4, bsd4, out, out_size);
}